// round 10
// baseline (speedup 1.0000x reference)
#include <cuda_runtime.h>
#include <cuda_bf16.h>
#include <cstdint>

#define N_ROIS   32768
#define N_GT     1024
#define N_IMAGES 8
#define NT       1024
#define NB       148                 // one block per SM, single wave

// approx-rcp IoU argmax step (comparisons only)
#define IOU_STEP(J, BB, BJ) {                                   \
    float4 g  = sbox[J];                                        \
    float iw  = fminf(rx2p, g.z) - fmaxf(rx1, g.x);             \
    float ih  = fminf(ry2p, g.w) - fmaxf(ry1, g.y);             \
    float inter = fmaxf(iw, 0.0f) * ih;                         \
    float uni = (g.z - g.x) * (g.w - g.y) + (area_r - inter);   \
    float iouv = __fdividef(inter, uni);                        \
    bool better = iouv > (BB);                                  \
    BB = better ? iouv : (BB);                                  \
    BJ = better ? (J)  : (BJ);                                  \
}

// merge: greater iou wins; exact tie -> smaller j (sentinel -1 never wins ties)
#define MERGE(OB, OJ) {                                         \
    bool take = ((OB) > best) ||                                \
        ((OB) == best && (unsigned)(OJ) < (unsigned)bj);        \
    best = take ? (OB) : best;                                  \
    bj   = take ? (OJ) : bj;                                    \
}

__global__ void __launch_bounds__(NT, 1) roitarget_fused(const float* __restrict__ rois,
                                                         const int* __restrict__ rb,
                                                         const float* __restrict__ gt,
                                                         const int* __restrict__ gb,
                                                         float* __restrict__ out) {
    __shared__ float4 sbox[N_GT];          // 16KB compacted x1,y1,x2+1,y2+1
    __shared__ float  slab[N_GT];          // 4KB labels
    __shared__ float4 sroi[256];           // 4KB ROI coords by local index
    __shared__ int    sgcnt[32][9];        // per-chunk per-batch GT counts (padded)
    __shared__ int    sexcl[32][9];        // exclusive chunk prefix (padded)
    __shared__ int    stot[N_IMAGES];
    __shared__ int    soff[N_IMAGES + 1];
    __shared__ int    swc[8][8];           // ROI counts per warp/batch
    __shared__ int    wbase[8][8];
    __shared__ int    sprovb[256], sprovr[256];
    __shared__ int    ssrc[256];           // sorted pos -> local ROI index
    __shared__ int    ssb[256];            // sorted pos -> batch

    const int tid  = threadIdx.x;
    const int w    = tid >> 5;
    const int lane = tid & 31;
    const unsigned lt = (1u << lane) - 1u;

    const int start = (blockIdx.x * N_ROIS) / NB;
    const int next  = ((blockIdx.x + 1) * N_ROIS) / NB;
    const int nroi  = next - start;        // 221 or 222

    // ---- hoisted global loads (latency overlapped with ballot phase) ----
    const int ba = gb[tid];                // 1 GT per thread
    const float a0 = gt[5*tid+0], a1 = gt[5*tid+1], a2 = gt[5*tid+2],
                a3 = gt[5*tid+3], a4 = gt[5*tid+4];
    int myb = -1;
    if (tid < nroi) {
        const int i = start + tid;
        myb = rb[i];
        sroi[tid] = make_float4(rois[5*i+0], rois[5*i+1], rois[5*i+2], rois[5*i+3]);
    }

    // ---- ballot counting: GT chunks (all 32 warps, chunk = w) ----
    int ranka = 0;
#pragma unroll
    for (int b = 0; b < N_IMAGES; b++) {
        unsigned ma = __ballot_sync(0xffffffffu, ba == b);
        if (ba == b) ranka = __popc(ma & lt);
        if (lane == 0) sgcnt[w][b] = __popc(ma);
    }
    // ---- ballot counting: ROIs (warps 0-7) ----
    if (w < 8) {
        int rank = 0;
#pragma unroll
        for (int b = 0; b < N_IMAGES; b++) {
            unsigned m = __ballot_sync(0xffffffffu, myb == b);
            if (myb == b) rank = __popc(m & lt);
            if (lane == 0) swc[w][b] = __popc(m);
        }
        if (tid < 256) { sprovb[tid] = myb; sprovr[tid] = rank; }
    }
    __syncthreads();                       // sync 1

    // ---- scans in parallel: warps 0-7 GT chunk-scan; warps 8-9 ROI bases ----
    if (w < N_IMAGES) {
        int v = sgcnt[lane][w];
        int incl = v;
#pragma unroll
        for (int d = 1; d < 32; d <<= 1) {
            int t = __shfl_up_sync(0xffffffffu, incl, d);
            if (lane >= d) incl += t;
        }
        sexcl[lane][w] = incl - v;
        if (lane == 31) stot[w] = incl;
    } else if (w == 8 || w == 9) {
        int e = (w - 8) * 32 + lane;       // 0..63
        int ww = e >> 3, b2 = e & 7;
        int o = 0;
        for (int b3 = 0; b3 < b2; b3++)
#pragma unroll
            for (int w2 = 0; w2 < 8; w2++) o += swc[w2][b3];
        for (int w2 = 0; w2 < ww; w2++) o += swc[w2][b2];
        wbase[ww][b2] = o;
    }
    __syncthreads();                       // sync 2

    // ---- per-warp redundant soff compute (identical values; no extra barrier)
    if (lane == 0) {
        int o = 0;
#pragma unroll
        for (int b = 0; b < N_IMAGES; b++) { soff[b] = o; o += stot[b]; }
        soff[N_IMAGES] = o;
    }
    __syncwarp();

    // ---- GT scatter (1 per thread, data in registers) ----
    {
        int da = soff[ba] + sexcl[w][ba] + ranka;
        sbox[da] = make_float4(a0, a1, a2 + 1.0f, a3 + 1.0f);
        slab[da] = a4;
    }
    // ---- ROI scatter (warps 0-7) ----
    if (tid < nroi) {
        int pb = sprovb[tid];
        int dest = wbase[w][pb] + sprovr[tid];
        ssrc[dest] = tid;                  // local index
        ssb[dest]  = pb;
    }
    __syncthreads();                       // sync 3

    // ---------------- Phase 3: 4 threads per ROI, interleaved quarters -----
    const int s = tid >> 2;                // ROI slot 0..255
    const int q = tid & 3;                 // quarter
    const bool valid = (s < nroi);
    const int loc = valid ? ssrc[s] : 0;
    const int b   = valid ? ssb[s]  : 0;

    const float4 rr = sroi[loc];
    const float rx1 = rr.x, ry1 = rr.y;
    const float rx2p = rr.z + 1.0f;
    const float ry2p = rr.w + 1.0f;
    const float ew = (rr.z - rx1) + 1.0f;
    const float eh = (rr.w - ry1) + 1.0f;
    const float area_r = ew * eh;

    const int j0 = valid ? soff[b]     : 0;
    const int j1 = valid ? soff[b + 1] : 0;
    const int len = j1 - j0;
    const int nfull = len >> 4;

    float bb0 = 0.0f; int bj0 = -1;
    float bb1 = 0.0f; int bj1 = -1;
    float bb3 = 0.0f; int bj3 = -1;
    float bb4 = 0.0f; int bj4 = -1;

    int base = j0 + q;
    for (int t = 0; t < nfull; t++, base += 16) {
        IOU_STEP(base + 0,  bb0, bj0);
        IOU_STEP(base + 4,  bb1, bj1);
        IOU_STEP(base + 8,  bb3, bj3);
        IOU_STEP(base + 12, bb4, bj4);
    }
    for (int j = j0 + (nfull << 4) + q; j < j1; j += 4) {
        IOU_STEP(j, bb0, bj0);
    }

    // in-thread chain merge (ties -> smaller j)
    float best = bb0; int bj = bj0;
    MERGE(bb1, bj1);
    MERGE(bb3, bj3);
    MERGE(bb4, bj4);

    // cross-quarter butterfly merge (all lanes participate; idle slots carry -1)
#pragma unroll
    for (int d = 1; d <= 2; d <<= 1) {
        float ob = __shfl_xor_sync(0xffffffffu, best, d);
        int   oj = __shfl_xor_sync(0xffffffffu, bj, d);
        MERGE(ob, oj);
    }

    if (q == 0 && valid) {
        const bool fg = (bj >= 0) && (best >= 0.5f);
        const int ii = start + loc;

        float lbl = 0.0f, dx = 0.0f, dy = 0.0f, dw = 0.0f, dh = 0.0f, wgt = 0.0f;
        if (fg) {
            float4 g = sbox[bj];
            float gw  = g.z - g.x;             // (x2+1) - x1
            float gh  = g.w - g.y;
            float gcx = g.x + 0.5f * gw;
            float gcy = g.y + 0.5f * gh;
            float ecx = rx1 + 0.5f * ew;
            float ecy = ry1 + 0.5f * eh;
            dx = (gcx - ecx) / ew;             // precise: feeds output
            dy = (gcy - ecy) / eh;
            dw = logf(gw / ew);
            dh = logf(gh / eh);
            lbl = slab[bj];
            wgt = 1.0f;
        }

        // Layout: labels[N] | deltas[N][4] | bbwgts[N][1]
        out[ii] = lbl;
        reinterpret_cast<float4*>(out + N_ROIS)[ii] = make_float4(dx, dy, dw, dh);
        out[N_ROIS * 5 + ii] = wgt;
    }
}

extern "C" void kernel_launch(void* const* d_in, const int* in_sizes, int n_in,
                              void* d_out, int out_size) {
    const float* rois = (const float*)d_in[0];
    const int*   rb   = (const int*)d_in[1];
    const float* gt   = (const float*)d_in[2];
    const int*   gb   = (const int*)d_in[3];
    float* out = (float*)d_out;

    roitarget_fused<<<NB, NT>>>(rois, rb, gt, gb, out);
}

// round 11
// speedup vs baseline: 1.0200x; 1.0200x over previous
#include <cuda_runtime.h>
#include <cuda_bf16.h>
#include <cstdint>

#define N_ROIS   32768
#define N_GT     1024
#define N_IMAGES 8
#define NT       1024
#define NB       148                 // one block per SM, single wave
#define NGT_PAD  1152                // 1024 + 8*16 max padding

// approx-rcp IoU argmax step (comparisons only); ag from sarea
#define IOU_STEP(J, BB, BJ) {                                   \
    float4 g  = sbox[J];                                        \
    float ag  = sarea[J];                                       \
    float iw  = fminf(rx2p, g.z) - fmaxf(rx1, g.x);             \
    float ih  = fminf(ry2p, g.w) - fmaxf(ry1, g.y);             \
    float inter = fmaxf(iw, 0.0f) * ih;                         \
    float uni = (area_r + ag) - inter;                          \
    float iouv = __fdividef(inter, uni);                        \
    bool better = iouv > (BB);                                  \
    BB = better ? iouv : (BB);                                  \
    BJ = better ? (J)  : (BJ);                                  \
}

// merge: greater iou wins; exact tie -> smaller j (sentinel -1 never wins ties)
#define MERGE(OB, OJ) {                                         \
    bool take = ((OB) > best) ||                                \
        ((OB) == best && (unsigned)(OJ) < (unsigned)bj);        \
    best = take ? (OB) : best;                                  \
    bj   = take ? (OJ) : bj;                                    \
}

__global__ void __launch_bounds__(NT, 1) roitarget_fused(const float* __restrict__ rois,
                                                         const int* __restrict__ rb,
                                                         const float* __restrict__ gt,
                                                         const int* __restrict__ gb,
                                                         float* __restrict__ out) {
    __shared__ float  sgt[5 * N_GT];       // 20KB raw staged gt (coalesced)
    __shared__ float4 sbox[NGT_PAD];       // 18.4KB compacted x1,y1,x2+1,y2+1 (+pads)
    __shared__ float  sarea[NGT_PAD];      // 4.6KB areas (+pads)
    __shared__ float  slab[NGT_PAD];       // 4.6KB labels
    __shared__ float4 sroi[256];           // 4KB ROI coords by local index
    __shared__ int    sgcnt[32][9];        // per-chunk per-batch GT counts (padded)
    __shared__ int    sexcl[32][9];        // exclusive chunk prefix (padded)
    __shared__ int    stot[N_IMAGES];
    __shared__ int    soff[N_IMAGES + 1];  // PADDED batch offsets
    __shared__ int    swc[8][8];           // ROI counts per warp/batch
    __shared__ int    wbase[8][8];
    __shared__ int    sprovb[256], sprovr[256];
    __shared__ int    ssrc[256];           // sorted pos -> local ROI index
    __shared__ int    ssb[256];            // sorted pos -> batch

    const int tid  = threadIdx.x;
    const int w    = tid >> 5;
    const int lane = tid & 31;
    const unsigned lt = (1u << lane) - 1u;

    const int start = (blockIdx.x * N_ROIS) / NB;
    const int next  = ((blockIdx.x + 1) * N_ROIS) / NB;
    const int nroi  = next - start;        // 221 or 222

    // ---- coalesced GT staging + hoisted loads (overlap ballot phase) ----
#pragma unroll
    for (int k = 0; k < 5; k++) sgt[tid + k * NT] = gt[tid + k * NT];
    const int ba = gb[tid];                // 1 GT per thread
    int myb = -1;
    if (tid < nroi) {
        const int i = start + tid;
        myb = rb[i];
        sroi[tid] = make_float4(rois[5*i+0], rois[5*i+1], rois[5*i+2], rois[5*i+3]);
    }

    // ---- ballot counting: GT chunks (all 32 warps, chunk = w) ----
    int ranka = 0;
#pragma unroll
    for (int b = 0; b < N_IMAGES; b++) {
        unsigned ma = __ballot_sync(0xffffffffu, ba == b);
        if (ba == b) ranka = __popc(ma & lt);
        if (lane == 0) sgcnt[w][b] = __popc(ma);
    }
    // ---- ballot counting: ROIs (warps 0-7) ----
    if (w < 8) {
        int rank = 0;
#pragma unroll
        for (int b = 0; b < N_IMAGES; b++) {
            unsigned m = __ballot_sync(0xffffffffu, myb == b);
            if (myb == b) rank = __popc(m & lt);
            if (lane == 0) swc[w][b] = __popc(m);
        }
        if (tid < 256) { sprovb[tid] = myb; sprovr[tid] = rank; }
    }
    __syncthreads();                       // sync 1

    // ---- scans in parallel: warps 0-7 GT chunk-scan; warps 8-9 ROI bases ----
    if (w < N_IMAGES) {
        int v = sgcnt[lane][w];
        int incl = v;
#pragma unroll
        for (int d = 1; d < 32; d <<= 1) {
            int t = __shfl_up_sync(0xffffffffu, incl, d);
            if (lane >= d) incl += t;
        }
        sexcl[lane][w] = incl - v;
        if (lane == 31) stot[w] = incl;
    } else if (w == 8 || w == 9) {
        int e = (w - 8) * 32 + lane;       // 0..63
        int ww = e >> 3, b2 = e & 7;
        int o = 0;
        for (int b3 = 0; b3 < b2; b3++)
#pragma unroll
            for (int w2 = 0; w2 < 8; w2++) o += swc[w2][b3];
        for (int w2 = 0; w2 < ww; w2++) o += swc[w2][b2];
        wbase[ww][b2] = o;
    }
    __syncthreads();                       // sync 2

    // ---- per-warp redundant PADDED offsets (identical values; no barrier) ----
    if (lane == 0) {
        int o = 0;
#pragma unroll
        for (int b = 0; b < N_IMAGES; b++) { soff[b] = o; o += (stot[b] + 15) & ~15; }
        soff[N_IMAGES] = o;
    }
    __syncwarp();

    // ---- GT parse from staged smem (stride-5 LDS: conflict-free) + scatter ----
    {
        const float x1 = sgt[5*tid+0], y1 = sgt[5*tid+1];
        const float x2 = sgt[5*tid+2], y2 = sgt[5*tid+3], cls = sgt[5*tid+4];
        const int da = soff[ba] + sexcl[w][ba] + ranka;
        sbox[da]  = make_float4(x1, y1, x2 + 1.0f, y2 + 1.0f);
        sarea[da] = ((x2 - x1) + 1.0f) * ((y2 - y1) + 1.0f);
        slab[da]  = cls;
    }
    // ---- write pad entries (never win: inter == 0, uni > 0) ----
    if (tid < 128) {
        const int b = tid >> 4, k = tid & 15;
        const int cnt  = stot[b];
        const int plen = (cnt + 15) & ~15;
        if (k < plen - cnt) {
            const int slot = soff[b] + cnt + k;
            sbox[slot]  = make_float4(3e9f, 0.0f, 1e9f, 1e9f);
            sarea[slot] = 1.0f;
            slab[slot]  = 0.0f;
        }
    }
    // ---- ROI scatter (warps 0-7) ----
    if (tid < nroi) {
        int pb = sprovb[tid];
        int dest = wbase[w][pb] + sprovr[tid];
        ssrc[dest] = tid;                  // local index
        ssb[dest]  = pb;
    }
    __syncthreads();                       // sync 3

    // ---------------- Phase 3: 4 threads per ROI, interleaved quarters -----
    const int s = tid >> 2;                // ROI slot 0..255
    const int q = tid & 3;                 // quarter
    const bool valid = (s < nroi);
    const int loc = valid ? ssrc[s] : 0;
    const int b   = valid ? ssb[s]  : 0;

    const float4 rr = sroi[loc];
    const float rx1 = rr.x, ry1 = rr.y;
    const float rx2p = rr.z + 1.0f;
    const float ry2p = rr.w + 1.0f;
    const float ew = (rr.z - rx1) + 1.0f;
    const float eh = (rr.w - ry1) + 1.0f;
    const float area_r = ew * eh;

    const int j0 = soff[b];
    const int nfull = valid ? (((stot[b] + 15) & ~15) >> 4) : 0;

    float bb0 = 0.0f; int bj0 = -1;
    float bb1 = 0.0f; int bj1 = -1;
    float bb3 = 0.0f; int bj3 = -1;
    float bb4 = 0.0f; int bj4 = -1;

    int base = j0 + q;
    for (int t = 0; t < nfull; t++, base += 16) {
        IOU_STEP(base + 0,  bb0, bj0);
        IOU_STEP(base + 4,  bb1, bj1);
        IOU_STEP(base + 8,  bb3, bj3);
        IOU_STEP(base + 12, bb4, bj4);
    }

    // in-thread chain merge (ties -> smaller j)
    float best = bb0; int bj = bj0;
    MERGE(bb1, bj1);
    MERGE(bb3, bj3);
    MERGE(bb4, bj4);

    // cross-quarter butterfly merge (all lanes participate; idle slots carry -1)
#pragma unroll
    for (int d = 1; d <= 2; d <<= 1) {
        float ob = __shfl_xor_sync(0xffffffffu, best, d);
        int   oj = __shfl_xor_sync(0xffffffffu, bj, d);
        MERGE(ob, oj);
    }

    if (q == 0 && valid) {
        const bool fg = (bj >= 0) && (best >= 0.5f);
        const int ii = start + loc;

        float lbl = 0.0f, dx = 0.0f, dy = 0.0f, dw = 0.0f, dh = 0.0f, wgt = 0.0f;
        if (fg) {
            float4 g = sbox[bj];
            float gw  = g.z - g.x;             // (x2+1) - x1
            float gh  = g.w - g.y;
            float gcx = g.x + 0.5f * gw;
            float gcy = g.y + 0.5f * gh;
            float ecx = rx1 + 0.5f * ew;
            float ecy = ry1 + 0.5f * eh;
            dx = (gcx - ecx) / ew;             // precise: feeds output
            dy = (gcy - ecy) / eh;
            dw = logf(gw / ew);
            dh = logf(gh / eh);
            lbl = slab[bj];
            wgt = 1.0f;
        }

        // Layout: labels[N] | deltas[N][4] | bbwgts[N][1]
        out[ii] = lbl;
        reinterpret_cast<float4*>(out + N_ROIS)[ii] = make_float4(dx, dy, dw, dh);
        out[N_ROIS * 5 + ii] = wgt;
    }
}

extern "C" void kernel_launch(void* const* d_in, const int* in_sizes, int n_in,
                              void* d_out, int out_size) {
    const float* rois = (const float*)d_in[0];
    const int*   rb   = (const int*)d_in[1];
    const float* gt   = (const float*)d_in[2];
    const int*   gb   = (const int*)d_in[3];
    float* out = (float*)d_out;

    roitarget_fused<<<NB, NT>>>(rois, rb, gt, gb, out);
}